// round 1
// baseline (speedup 1.0000x reference)
#include <cuda_runtime.h>
#include <math.h>
#include <stddef.h>

#define BB   2
#define SS   1024
#define DD   1024
#define HH   16
#define DKK  64
#define LL   4
#define DFFN 4096
#define OUTV 32000
#define MTOK (BB*SS)

// ---------------- scratch (allocation-free: __device__ globals) ----------------
__device__ float g_h[MTOK*DD];
__device__ float g_q[MTOK*DD];
__device__ float g_k[MTOK*DD];
__device__ float g_v[MTOK*DD];
__device__ float g_attn[MTOK*DD];
__device__ float g_tmp[MTOK*DD];
__device__ float g_ffn[(size_t)MTOK*DFFN];
__device__ float g_scores[(size_t)BB*HH*SS*SS];   // 128 MB

// ---------------- embedding ----------------
__global__ void embed_kernel(const int* __restrict__ x, const float* __restrict__ emb,
                             float* __restrict__ h) {
    int r = blockIdx.x;
    int tok = x[r];
    const float4* src = (const float4*)(emb + (size_t)tok * DD);
    float4* dst = (float4*)(h + (size_t)r * DD);
    float4 v = src[threadIdx.x];
    v.x *= 32.0f; v.y *= 32.0f; v.z *= 32.0f; v.w *= 32.0f;   // sqrt(1024)
    dst[threadIdx.x] = v;
}

// ---------------- generic NN GEMM: C = A(MxK) * B(KxN) + bias, epilogue modes ----
// mode 0: plain  1: exact gelu  2: output-mask by start_pos
__global__ void __launch_bounds__(256) gemm_nn(
    const float* __restrict__ A, const float* __restrict__ Bm,
    const float* __restrict__ bias, float* __restrict__ C,
    int M, int N, int K, int lda, int ldb, int ldc,
    int mode, const int* __restrict__ start_pos)
{
    __shared__ float As[16][68];
    __shared__ float Bs[16][64];
    int tx = threadIdx.x, ty = threadIdx.y;
    int t = ty * 16 + tx;
    int row0 = blockIdx.y * 64, col0 = blockIdx.x * 64;
    int arow = t >> 2, acol = (t & 3) << 2;
    int brow = t >> 4, bcol = (t & 15) << 2;

    const float* Ap = A + (size_t)(row0 + arow) * lda + acol;
    const float* Bp = Bm + (size_t)brow * ldb + col0 + bcol;

    float acc[4][4] = {};
    for (int k0 = 0; k0 < K; k0 += 16) {
        float4 av = *(const float4*)Ap; Ap += 16;
        float4 bv = *(const float4*)Bp; Bp += (size_t)16 * ldb;
        As[acol + 0][arow] = av.x;
        As[acol + 1][arow] = av.y;
        As[acol + 2][arow] = av.z;
        As[acol + 3][arow] = av.w;
        *(float4*)&Bs[brow][bcol] = bv;
        __syncthreads();
        #pragma unroll
        for (int kk = 0; kk < 16; kk++) {
            float4 a = *(const float4*)&As[kk][ty << 2];
            float4 b = *(const float4*)&Bs[kk][tx << 2];
            float a4[4] = {a.x, a.y, a.z, a.w};
            float b4[4] = {b.x, b.y, b.z, b.w};
            #pragma unroll
            for (int i = 0; i < 4; i++)
                #pragma unroll
                for (int j = 0; j < 4; j++)
                    acc[i][j] += a4[i] * b4[j];
        }
        __syncthreads();
    }

    #pragma unroll
    for (int i = 0; i < 4; i++) {
        int r = row0 + (ty << 2) + i;
        #pragma unroll
        for (int j = 0; j < 4; j++) {
            int c = col0 + (tx << 2) + j;
            float vv = acc[i][j];
            if (bias) vv += bias[c];
            if (mode == 1) {
                vv = 0.5f * vv * (1.0f + erff(vv * 0.70710678118654752f));
            } else if (mode == 2) {
                int bi = r >> 10, si = r & 1023;
                if (si < start_pos[bi]) vv = 0.0f;
            }
            C[(size_t)r * ldc + c] = vv;
        }
    }
}

// ---------------- attention scores: S[z, q, c] = sum_d Q[q,d]*K[c,d]  (NT) ------
__global__ void __launch_bounds__(256) attn_scores(
    const float* __restrict__ Q, const float* __restrict__ Kt, float* __restrict__ Sc)
{
    int z = blockIdx.z;
    int bi = z >> 4, hi = z & 15;
    const float* Ab = Q + (size_t)bi * SS * DD + hi * DKK;
    const float* Bb = Kt + (size_t)bi * SS * DD + hi * DKK;
    float* C = Sc + (size_t)z * SS * SS;

    __shared__ float As[16][68];
    __shared__ float Bs[16][68];
    int tx = threadIdx.x, ty = threadIdx.y;
    int t = ty * 16 + tx;
    int row0 = blockIdx.y * 64, col0 = blockIdx.x * 64;
    int arow = t >> 2, acol = (t & 3) << 2;

    const float* Ap = Ab + (size_t)(row0 + arow) * DD + acol;
    const float* Bp = Bb + (size_t)(col0 + arow) * DD + acol;

    float acc[4][4] = {};
    for (int k0 = 0; k0 < DKK; k0 += 16) {
        float4 av = *(const float4*)Ap; Ap += 16;
        float4 bv = *(const float4*)Bp; Bp += 16;
        As[acol + 0][arow] = av.x; As[acol + 1][arow] = av.y;
        As[acol + 2][arow] = av.z; As[acol + 3][arow] = av.w;
        Bs[acol + 0][arow] = bv.x; Bs[acol + 1][arow] = bv.y;
        Bs[acol + 2][arow] = bv.z; Bs[acol + 3][arow] = bv.w;
        __syncthreads();
        #pragma unroll
        for (int kk = 0; kk < 16; kk++) {
            float4 a = *(const float4*)&As[kk][ty << 2];
            float4 b = *(const float4*)&Bs[kk][tx << 2];
            float a4[4] = {a.x, a.y, a.z, a.w};
            float b4[4] = {b.x, b.y, b.z, b.w};
            #pragma unroll
            for (int i = 0; i < 4; i++)
                #pragma unroll
                for (int j = 0; j < 4; j++)
                    acc[i][j] += a4[i] * b4[j];
        }
        __syncthreads();
    }

    #pragma unroll
    for (int i = 0; i < 4; i++) {
        int r = row0 + (ty << 2) + i;
        #pragma unroll
        for (int j = 0; j < 4; j++) {
            int c = col0 + (tx << 2) + j;
            C[(size_t)r * SS + c] = acc[i][j];
        }
    }
}

// ---------------- softmax with scale + alibi + causal/start mask (in place) -----
__global__ void __launch_bounds__(256) softmax_kernel(
    float* __restrict__ Sc, const int* __restrict__ sp)
{
    int gid = blockIdx.x;           // z*S + q
    int q = gid & (SS - 1);
    int z = gid >> 10;
    int hi = z & 15, bi = z >> 4;
    float* row = Sc + (size_t)gid * SS;
    int spv = sp[bi];
    float slope = exp2f(-0.5f * (float)(hi + 1));
    int tid = threadIdx.x;

    float vals[4];
    float mx = -1e30f;
    #pragma unroll
    for (int i = 0; i < 4; i++) {
        int c = tid + i * 256;
        float v = row[c] * 0.125f + slope * (float)(c - q);
        bool ok = (q >= c) || (q < spv) || (c < spv);
        v = ok ? v : -1e9f;
        vals[i] = v;
        mx = fmaxf(mx, v);
    }
    __shared__ float red[256];
    red[tid] = mx; __syncthreads();
    for (int s = 128; s > 0; s >>= 1) {
        if (tid < s) red[tid] = fmaxf(red[tid], red[tid + s]);
        __syncthreads();
    }
    mx = red[0]; __syncthreads();

    float sum = 0.0f;
    #pragma unroll
    for (int i = 0; i < 4; i++) { vals[i] = expf(vals[i] - mx); sum += vals[i]; }
    red[tid] = sum; __syncthreads();
    for (int s = 128; s > 0; s >>= 1) {
        if (tid < s) red[tid] += red[tid + s];
        __syncthreads();
    }
    float inv = 1.0f / red[0];
    #pragma unroll
    for (int i = 0; i < 4; i++) row[tid + i * 256] = vals[i] * inv;
}

// ---------------- attn output: O[q, d] = sum_c P[q,c] * V[c,d]  (NN, N=64) ------
__global__ void __launch_bounds__(256) attn_pv(
    const float* __restrict__ P, const float* __restrict__ V, float* __restrict__ O)
{
    int z = blockIdx.z;
    int bi = z >> 4, hi = z & 15;
    const float* Ab = P + (size_t)z * SS * SS;                  // lda = SS
    const float* Bb = V + (size_t)bi * SS * DD + hi * DKK;      // ldb = DD
    float* C = O + (size_t)bi * SS * DD + hi * DKK;             // ldc = DD

    __shared__ float As[16][68];
    __shared__ float Bs[16][64];
    int tx = threadIdx.x, ty = threadIdx.y;
    int t = ty * 16 + tx;
    int row0 = blockIdx.y * 64;
    int arow = t >> 2, acol = (t & 3) << 2;
    int brow = t >> 4, bcol = (t & 15) << 2;

    const float* Ap = Ab + (size_t)(row0 + arow) * SS + acol;
    const float* Bp = Bb + (size_t)brow * DD + bcol;

    float acc[4][4] = {};
    for (int k0 = 0; k0 < SS; k0 += 16) {
        float4 av = *(const float4*)Ap; Ap += 16;
        float4 bv = *(const float4*)Bp; Bp += (size_t)16 * DD;
        As[acol + 0][arow] = av.x; As[acol + 1][arow] = av.y;
        As[acol + 2][arow] = av.z; As[acol + 3][arow] = av.w;
        *(float4*)&Bs[brow][bcol] = bv;
        __syncthreads();
        #pragma unroll
        for (int kk = 0; kk < 16; kk++) {
            float4 a = *(const float4*)&As[kk][ty << 2];
            float4 b = *(const float4*)&Bs[kk][tx << 2];
            float a4[4] = {a.x, a.y, a.z, a.w};
            float b4[4] = {b.x, b.y, b.z, b.w};
            #pragma unroll
            for (int i = 0; i < 4; i++)
                #pragma unroll
                for (int j = 0; j < 4; j++)
                    acc[i][j] += a4[i] * b4[j];
        }
        __syncthreads();
    }

    #pragma unroll
    for (int i = 0; i < 4; i++) {
        int r = row0 + (ty << 2) + i;
        #pragma unroll
        for (int j = 0; j < 4; j++) {
            int c = (tx << 2) + j;
            C[(size_t)r * DD + c] = acc[i][j];
        }
    }
}

// ---------------- residual add + layernorm (row per block) ----------------------
__global__ void __launch_bounds__(256) add_ln(
    const float* __restrict__ X, const float* __restrict__ Rs,
    const float* __restrict__ g, const float* __restrict__ bta,
    float* __restrict__ out)
{
    int r = blockIdx.x, tid = threadIdx.x;
    const float4* x4 = (const float4*)(X + (size_t)r * DD);
    const float4* r4 = (const float4*)(Rs + (size_t)r * DD);
    float4 xv = x4[tid], rv = r4[tid];
    float v0 = xv.x + rv.x, v1 = xv.y + rv.y, v2 = xv.z + rv.z, v3 = xv.w + rv.w;
    float s1 = v0 + v1 + v2 + v3;
    float s2 = v0*v0 + v1*v1 + v2*v2 + v3*v3;

    __shared__ float rA[256], rB[256];
    rA[tid] = s1; rB[tid] = s2; __syncthreads();
    for (int s = 128; s > 0; s >>= 1) {
        if (tid < s) { rA[tid] += rA[tid + s]; rB[tid] += rB[tid + s]; }
        __syncthreads();
    }
    float mu = rA[0] * (1.0f / 1024.0f);
    float var = rB[0] * (1.0f / 1024.0f) - mu * mu;
    float rstd = rsqrtf(var + 1e-5f);

    const float4 gv = ((const float4*)g)[tid];
    const float4 bv = ((const float4*)bta)[tid];
    float4 o;
    o.x = (v0 - mu) * rstd * gv.x + bv.x;
    o.y = (v1 - mu) * rstd * gv.y + bv.y;
    o.z = (v2 - mu) * rstd * gv.z + bv.z;
    o.w = (v3 - mu) * rstd * gv.w + bv.w;
    ((float4*)(out + (size_t)r * DD))[tid] = o;
}

// ---------------- launch ----------------
extern "C" void kernel_launch(void* const* d_in, const int* in_sizes, int n_in,
                              void* d_out, int out_size) {
    (void)in_sizes; (void)n_in; (void)out_size;
    const int*   x    = (const int*)  d_in[0];
    const int*   sp   = (const int*)  d_in[1];
    const float* emb  = (const float*)d_in[2];
    const float* Wq   = (const float*)d_in[3];
    const float* bq   = (const float*)d_in[4];
    const float* Wk   = (const float*)d_in[5];
    const float* bk   = (const float*)d_in[6];
    const float* Wv   = (const float*)d_in[7];
    const float* bv   = (const float*)d_in[8];
    const float* Wo   = (const float*)d_in[9];
    const float* bo   = (const float*)d_in[10];
    const float* ln1g = (const float*)d_in[11];
    const float* ln1b = (const float*)d_in[12];
    const float* W1   = (const float*)d_in[13];
    const float* b1   = (const float*)d_in[14];
    const float* W2   = (const float*)d_in[15];
    const float* b2   = (const float*)d_in[16];
    const float* ln2g = (const float*)d_in[17];
    const float* ln2b = (const float*)d_in[18];
    const float* fcw  = (const float*)d_in[19];
    const float* fcb  = (const float*)d_in[20];
    float* out = (float*)d_out;

    float *h, *q, *k, *v, *attn, *tmp, *ffn, *scores;
    cudaGetSymbolAddress((void**)&h,      g_h);
    cudaGetSymbolAddress((void**)&q,      g_q);
    cudaGetSymbolAddress((void**)&k,      g_k);
    cudaGetSymbolAddress((void**)&v,      g_v);
    cudaGetSymbolAddress((void**)&attn,   g_attn);
    cudaGetSymbolAddress((void**)&tmp,    g_tmp);
    cudaGetSymbolAddress((void**)&ffn,    g_ffn);
    cudaGetSymbolAddress((void**)&scores, g_scores);

    dim3 thr(16, 16);

    embed_kernel<<<MTOK, 256>>>(x, emb, h);

    for (int l = 0; l < LL; l++) {
        const float* Wql = Wq + (size_t)l * DD * DD;
        const float* Wkl = Wk + (size_t)l * DD * DD;
        const float* Wvl = Wv + (size_t)l * DD * DD;
        const float* Wol = Wo + (size_t)l * DD * DD;
        const float* W1l = W1 + (size_t)l * DD * DFFN;
        const float* W2l = W2 + (size_t)l * DFFN * DD;

        gemm_nn<<<dim3(DD/64, MTOK/64), thr>>>(h, Wql, bq + (size_t)l*DD, q,
            MTOK, DD, DD, DD, DD, DD, 0, (const int*)0);
        gemm_nn<<<dim3(DD/64, MTOK/64), thr>>>(h, Wkl, bk + (size_t)l*DD, k,
            MTOK, DD, DD, DD, DD, DD, 0, (const int*)0);
        gemm_nn<<<dim3(DD/64, MTOK/64), thr>>>(h, Wvl, bv + (size_t)l*DD, v,
            MTOK, DD, DD, DD, DD, DD, 0, (const int*)0);

        attn_scores<<<dim3(SS/64, SS/64, BB*HH), thr>>>(q, k, scores);
        softmax_kernel<<<BB*HH*SS, 256>>>(scores, sp);
        attn_pv<<<dim3(1, SS/64, BB*HH), thr>>>(scores, v, attn);

        gemm_nn<<<dim3(DD/64, MTOK/64), thr>>>(attn, Wol, bo + (size_t)l*DD, tmp,
            MTOK, DD, DD, DD, DD, DD, 0, (const int*)0);
        add_ln<<<MTOK, 256>>>(h, tmp, ln1g + (size_t)l*DD, ln1b + (size_t)l*DD, h);

        gemm_nn<<<dim3(DFFN/64, MTOK/64), thr>>>(h, W1l, b1 + (size_t)l*DFFN, ffn,
            MTOK, DFFN, DD, DD, DFFN, DFFN, 1, (const int*)0);
        gemm_nn<<<dim3(DD/64, MTOK/64), thr>>>(ffn, W2l, b2 + (size_t)l*DD, tmp,
            MTOK, DD, DFFN, DFFN, DD, DD, 0, (const int*)0);
        add_ln<<<MTOK, 256>>>(h, tmp, ln2g + (size_t)l*DD, ln2b + (size_t)l*DD, h);
    }

    gemm_nn<<<dim3(OUTV/64, MTOK/64), thr>>>(h, fcw, fcb, out,
        MTOK, OUTV, DD, DD, OUTV, OUTV, 2, sp);
}

// round 2
// speedup vs baseline: 2.2278x; 2.2278x over previous
#include <cuda_runtime.h>
#include <math.h>
#include <stddef.h>
#include <stdint.h>

#define BB   2
#define SS   1024
#define DD   1024
#define HH   16
#define DKK  64
#define LL   4
#define DFFN 4096
#define OUTV 32000
#define MTOK (BB*SS)

// ---------------- scratch (allocation-free: __device__ globals) ----------------
__device__ float g_h[MTOK*DD];
__device__ float g_q[MTOK*DD];
__device__ float g_k[MTOK*DD];
__device__ float g_v[MTOK*DD];
__device__ float g_attn[MTOK*DD];
__device__ float g_tmp[MTOK*DD];
__device__ float g_ffn[(size_t)MTOK*DFFN];
__device__ float g_scores[(size_t)BB*HH*SS*SS];   // 128 MB

// ---------------- embedding ----------------
__global__ void embed_kernel(const int* __restrict__ x, const float* __restrict__ emb,
                             float* __restrict__ h) {
    int r = blockIdx.x;
    int tok = x[r];
    const float4* src = (const float4*)(emb + (size_t)tok * DD);
    float4* dst = (float4*)(h + (size_t)r * DD);
    float4 v = src[threadIdx.x];
    v.x *= 32.0f; v.y *= 32.0f; v.z *= 32.0f; v.w *= 32.0f;   // sqrt(1024)
    dst[threadIdx.x] = v;
}

// ---------------- tf32 helpers ----------------
__device__ __forceinline__ float tf32r(float x) {
    uint32_t u;
    asm("cvt.rna.tf32.f32 %0, %1;" : "=r"(u) : "f"(x));
    return __uint_as_float(u);
}

__device__ __forceinline__ void mma_tf32(float* c, const uint32_t* a, const uint32_t* b) {
    asm volatile(
        "mma.sync.aligned.m16n8k8.row.col.f32.tf32.tf32.f32 "
        "{%0,%1,%2,%3}, {%4,%5,%6,%7}, {%8,%9}, {%0,%1,%2,%3};"
        : "+f"(c[0]), "+f"(c[1]), "+f"(c[2]), "+f"(c[3])
        : "r"(a[0]), "r"(a[1]), "r"(a[2]), "r"(a[3]), "r"(b[0]), "r"(b[1]));
}

// ---------------- tf32 tensor-core GEMM: C = A(MxK) * B(KxN) + bias -------------
// Block tile 128x128, K-chunk 16, double-buffered SMEM, 8 warps (2x4), each warp
// 64x32 via 4x4 grid of m16n8k8 fragments.
// mode 0: plain  1: exact gelu  2: output-mask by start_pos
// Requirements: M%128==0, N%128==0, K%16==0 (true for all call sites).
#define BM 128
#define BN 128
#define BKC 16
#define LDA_S 20     // conflict-free: (20*r + c) % 32 distinct for r 0..7, c 0..3
#define LDB_S 136    // conflict-free: (136*k + n) % 32 = (8k+n)%32 distinct

__global__ void __launch_bounds__(256) gemm_tf32(
    const float* __restrict__ A, const float* __restrict__ Bm,
    const float* __restrict__ bias, float* __restrict__ C,
    int M, int N, int K, int lda, int ldb, int ldc,
    int mode, const int* __restrict__ start_pos)
{
    __shared__ __align__(16) float As[2][BM * LDA_S];
    __shared__ __align__(16) float Bs[2][BKC * LDB_S];

    int tid = threadIdx.x;
    int lane = tid & 31, warp = tid >> 5;
    int warp_m = warp >> 2, warp_n = warp & 3;      // 2 x 4 warps
    int g = lane >> 2, tg = lane & 3;
    int row0 = blockIdx.x * BM, col0 = blockIdx.y * BN;

    const float* Abase = A + (size_t)row0 * lda;
    const float* Bbase = Bm + col0;

    // global staging regs
    float4 ra0, ra1, rb0, rb1;
    int afr0 = tid >> 2,        afc0 = (tid & 3) << 2;
    int afr1 = (tid + 256) >> 2, afc1 = ((tid + 256) & 3) << 2;
    int bfr0 = tid >> 5,        bfc0 = (tid & 31) << 2;
    int bfr1 = (tid + 256) >> 5, bfc1 = ((tid + 256) & 31) << 2;

    // ---- prologue: chunk 0 ----
    ra0 = *(const float4*)(Abase + (size_t)afr0 * lda + afc0);
    ra1 = *(const float4*)(Abase + (size_t)afr1 * lda + afc1);
    rb0 = *(const float4*)(Bbase + (size_t)bfr0 * ldb + bfc0);
    rb1 = *(const float4*)(Bbase + (size_t)bfr1 * ldb + bfc1);
    {
        float4 c0 = make_float4(tf32r(ra0.x), tf32r(ra0.y), tf32r(ra0.z), tf32r(ra0.w));
        float4 c1 = make_float4(tf32r(ra1.x), tf32r(ra1.y), tf32r(ra1.z), tf32r(ra1.w));
        *(float4*)&As[0][afr0 * LDA_S + afc0] = c0;
        *(float4*)&As[0][afr1 * LDA_S + afc1] = c1;
        float4 d0 = make_float4(tf32r(rb0.x), tf32r(rb0.y), tf32r(rb0.z), tf32r(rb0.w));
        float4 d1 = make_float4(tf32r(rb1.x), tf32r(rb1.y), tf32r(rb1.z), tf32r(rb1.w));
        *(float4*)&Bs[0][bfr0 * LDB_S + bfc0] = d0;
        *(float4*)&Bs[0][bfr1 * LDB_S + bfc1] = d1;
    }
    __syncthreads();

    float acc[4][4][4] = {};

    int nch = K / BKC;
    for (int ch = 0; ch < nch; ch++) {
        int cur = ch & 1;
        if (ch + 1 < nch) {
            int k0 = (ch + 1) * BKC;
            ra0 = *(const float4*)(Abase + (size_t)afr0 * lda + k0 + afc0);
            ra1 = *(const float4*)(Abase + (size_t)afr1 * lda + k0 + afc1);
            rb0 = *(const float4*)(Bbase + (size_t)(k0 + bfr0) * ldb + bfc0);
            rb1 = *(const float4*)(Bbase + (size_t)(k0 + bfr1) * ldb + bfc1);
        }

        const float* as = As[cur];
        const float* bs = Bs[cur];
        #pragma unroll
        for (int ks = 0; ks < 2; ks++) {
            int kc = ks * 8;
            uint32_t af[4][4], bf[4][2];
            #pragma unroll
            for (int m = 0; m < 4; m++) {
                int mb = warp_m * 64 + m * 16;
                const float* base = as + (mb + g) * LDA_S + kc + tg;
                af[m][0] = __float_as_uint(base[0]);
                af[m][1] = __float_as_uint(base[8 * LDA_S]);
                af[m][2] = __float_as_uint(base[4]);
                af[m][3] = __float_as_uint(base[8 * LDA_S + 4]);
            }
            #pragma unroll
            for (int n = 0; n < 4; n++) {
                int nb = warp_n * 32 + n * 8;
                bf[n][0] = __float_as_uint(bs[(kc + tg) * LDB_S + nb + g]);
                bf[n][1] = __float_as_uint(bs[(kc + tg + 4) * LDB_S + nb + g]);
            }
            #pragma unroll
            for (int m = 0; m < 4; m++)
                #pragma unroll
                for (int n = 0; n < 4; n++)
                    mma_tf32(acc[m][n], af[m], bf[n]);
        }

        if (ch + 1 < nch) {
            int nxt = cur ^ 1;
            float4 c0 = make_float4(tf32r(ra0.x), tf32r(ra0.y), tf32r(ra0.z), tf32r(ra0.w));
            float4 c1 = make_float4(tf32r(ra1.x), tf32r(ra1.y), tf32r(ra1.z), tf32r(ra1.w));
            *(float4*)&As[nxt][afr0 * LDA_S + afc0] = c0;
            *(float4*)&As[nxt][afr1 * LDA_S + afc1] = c1;
            float4 d0 = make_float4(tf32r(rb0.x), tf32r(rb0.y), tf32r(rb0.z), tf32r(rb0.w));
            float4 d1 = make_float4(tf32r(rb1.x), tf32r(rb1.y), tf32r(rb1.z), tf32r(rb1.w));
            *(float4*)&Bs[nxt][bfr0 * LDB_S + bfc0] = d0;
            *(float4*)&Bs[nxt][bfr1 * LDB_S + bfc1] = d1;
        }
        __syncthreads();
    }

    // ---- epilogue ----
    #pragma unroll
    for (int m = 0; m < 4; m++) {
        int r0 = row0 + warp_m * 64 + m * 16 + g;
        #pragma unroll
        for (int n = 0; n < 4; n++) {
            int c = col0 + warp_n * 32 + n * 8 + tg * 2;
            float b0f = bias ? bias[c] : 0.0f;
            float b1f = bias ? bias[c + 1] : 0.0f;
            float v[4] = { acc[m][n][0] + b0f, acc[m][n][1] + b1f,
                           acc[m][n][2] + b0f, acc[m][n][3] + b1f };
            if (mode == 1) {
                #pragma unroll
                for (int i = 0; i < 4; i++)
                    v[i] = 0.5f * v[i] * (1.0f + erff(v[i] * 0.70710678118654752f));
            } else if (mode == 2) {
                int bi0 = r0 >> 10, si0 = r0 & 1023;
                int r1 = r0 + 8;
                int bi1 = r1 >> 10, si1 = r1 & 1023;
                if (si0 < start_pos[bi0]) { v[0] = 0.0f; v[1] = 0.0f; }
                if (si1 < start_pos[bi1]) { v[2] = 0.0f; v[3] = 0.0f; }
            }
            *(float2*)&C[(size_t)r0 * ldc + c]       = make_float2(v[0], v[1]);
            *(float2*)&C[(size_t)(r0 + 8) * ldc + c] = make_float2(v[2], v[3]);
        }
    }
}

// ---------------- attention scores: S[z, q, c] = sum_d Q[q,d]*K[c,d]  (NT) ------
__global__ void __launch_bounds__(256) attn_scores(
    const float* __restrict__ Q, const float* __restrict__ Kt, float* __restrict__ Sc)
{
    int z = blockIdx.z;
    int bi = z >> 4, hi = z & 15;
    const float* Ab = Q + (size_t)bi * SS * DD + hi * DKK;
    const float* Bb = Kt + (size_t)bi * SS * DD + hi * DKK;
    float* C = Sc + (size_t)z * SS * SS;

    __shared__ float As_[16][68];
    __shared__ float Bs_[16][68];
    int tx = threadIdx.x, ty = threadIdx.y;
    int t = ty * 16 + tx;
    int row0 = blockIdx.y * 64, col0 = blockIdx.x * 64;
    int arow = t >> 2, acol = (t & 3) << 2;

    const float* Ap = Ab + (size_t)(row0 + arow) * DD + acol;
    const float* Bp = Bb + (size_t)(col0 + arow) * DD + acol;

    float acc[4][4] = {};
    for (int k0 = 0; k0 < DKK; k0 += 16) {
        float4 av = *(const float4*)Ap; Ap += 16;
        float4 bv = *(const float4*)Bp; Bp += 16;
        As_[acol + 0][arow] = av.x; As_[acol + 1][arow] = av.y;
        As_[acol + 2][arow] = av.z; As_[acol + 3][arow] = av.w;
        Bs_[acol + 0][arow] = bv.x; Bs_[acol + 1][arow] = bv.y;
        Bs_[acol + 2][arow] = bv.z; Bs_[acol + 3][arow] = bv.w;
        __syncthreads();
        #pragma unroll
        for (int kk = 0; kk < 16; kk++) {
            float4 a = *(const float4*)&As_[kk][ty << 2];
            float4 b = *(const float4*)&Bs_[kk][tx << 2];
            float a4[4] = {a.x, a.y, a.z, a.w};
            float b4[4] = {b.x, b.y, b.z, b.w};
            #pragma unroll
            for (int i = 0; i < 4; i++)
                #pragma unroll
                for (int j = 0; j < 4; j++)
                    acc[i][j] += a4[i] * b4[j];
        }
        __syncthreads();
    }

    #pragma unroll
    for (int i = 0; i < 4; i++) {
        int r = row0 + (ty << 2) + i;
        #pragma unroll
        for (int j = 0; j < 4; j++) {
            int c = col0 + (tx << 2) + j;
            C[(size_t)r * SS + c] = acc[i][j];
        }
    }
}

// ---------------- softmax with scale + alibi + causal/start mask (in place) -----
__global__ void __launch_bounds__(256) softmax_kernel(
    float* __restrict__ Sc, const int* __restrict__ sp)
{
    int gid = blockIdx.x;           // z*S + q
    int q = gid & (SS - 1);
    int z = gid >> 10;
    int hi = z & 15, bi = z >> 4;
    float* row = Sc + (size_t)gid * SS;
    int spv = sp[bi];
    float slope = exp2f(-0.5f * (float)(hi + 1));
    int tid = threadIdx.x;

    float vals[4];
    float mx = -1e30f;
    #pragma unroll
    for (int i = 0; i < 4; i++) {
        int c = tid + i * 256;
        float v = row[c] * 0.125f + slope * (float)(c - q);
        bool ok = (q >= c) || (q < spv) || (c < spv);
        v = ok ? v : -1e9f;
        vals[i] = v;
        mx = fmaxf(mx, v);
    }
    __shared__ float red[256];
    red[tid] = mx; __syncthreads();
    for (int s = 128; s > 0; s >>= 1) {
        if (tid < s) red[tid] = fmaxf(red[tid], red[tid + s]);
        __syncthreads();
    }
    mx = red[0]; __syncthreads();

    float sum = 0.0f;
    #pragma unroll
    for (int i = 0; i < 4; i++) { vals[i] = expf(vals[i] - mx); sum += vals[i]; }
    red[tid] = sum; __syncthreads();
    for (int s = 128; s > 0; s >>= 1) {
        if (tid < s) red[tid] += red[tid + s];
        __syncthreads();
    }
    float inv = 1.0f / red[0];
    #pragma unroll
    for (int i = 0; i < 4; i++) row[tid + i * 256] = vals[i] * inv;
}

// ---------------- attn output: O[q, d] = sum_c P[q,c] * V[c,d]  (NN, N=64) ------
__global__ void __launch_bounds__(256) attn_pv(
    const float* __restrict__ P, const float* __restrict__ V, float* __restrict__ O)
{
    int z = blockIdx.z;
    int bi = z >> 4, hi = z & 15;
    const float* Ab = P + (size_t)z * SS * SS;
    const float* Bb = V + (size_t)bi * SS * DD + hi * DKK;
    float* C = O + (size_t)bi * SS * DD + hi * DKK;

    __shared__ float As_[16][68];
    __shared__ float Bs_[16][64];
    int tx = threadIdx.x, ty = threadIdx.y;
    int t = ty * 16 + tx;
    int row0 = blockIdx.y * 64;
    int arow = t >> 2, acol = (t & 3) << 2;
    int brow = t >> 4, bcol = (t & 15) << 2;

    const float* Ap = Ab + (size_t)(row0 + arow) * SS + acol;
    const float* Bp = Bb + (size_t)brow * DD + bcol;

    float acc[4][4] = {};
    for (int k0 = 0; k0 < SS; k0 += 16) {
        float4 av = *(const float4*)Ap; Ap += 16;
        float4 bv = *(const float4*)Bp; Bp += (size_t)16 * DD;
        As_[acol + 0][arow] = av.x; As_[acol + 1][arow] = av.y;
        As_[acol + 2][arow] = av.z; As_[acol + 3][arow] = av.w;
        *(float4*)&Bs_[brow][bcol] = bv;
        __syncthreads();
        #pragma unroll
        for (int kk = 0; kk < 16; kk++) {
            float4 a = *(const float4*)&As_[kk][ty << 2];
            float4 b = *(const float4*)&Bs_[kk][tx << 2];
            float a4[4] = {a.x, a.y, a.z, a.w};
            float b4[4] = {b.x, b.y, b.z, b.w};
            #pragma unroll
            for (int i = 0; i < 4; i++)
                #pragma unroll
                for (int j = 0; j < 4; j++)
                    acc[i][j] += a4[i] * b4[j];
        }
        __syncthreads();
    }

    #pragma unroll
    for (int i = 0; i < 4; i++) {
        int r = row0 + (ty << 2) + i;
        #pragma unroll
        for (int j = 0; j < 4; j++) {
            int c = (tx << 2) + j;
            C[(size_t)r * DD + c] = acc[i][j];
        }
    }
}

// ---------------- residual add + layernorm (row per block) ----------------------
__global__ void __launch_bounds__(256) add_ln(
    const float* __restrict__ X, const float* __restrict__ Rs,
    const float* __restrict__ g, const float* __restrict__ bta,
    float* __restrict__ out)
{
    int r = blockIdx.x, tid = threadIdx.x;
    const float4* x4 = (const float4*)(X + (size_t)r * DD);
    const float4* r4 = (const float4*)(Rs + (size_t)r * DD);
    float4 xv = x4[tid], rv = r4[tid];
    float v0 = xv.x + rv.x, v1 = xv.y + rv.y, v2 = xv.z + rv.z, v3 = xv.w + rv.w;
    float s1 = v0 + v1 + v2 + v3;
    float s2 = v0*v0 + v1*v1 + v2*v2 + v3*v3;

    __shared__ float rA[256], rB[256];
    rA[tid] = s1; rB[tid] = s2; __syncthreads();
    for (int s = 128; s > 0; s >>= 1) {
        if (tid < s) { rA[tid] += rA[tid + s]; rB[tid] += rB[tid + s]; }
        __syncthreads();
    }
    float mu = rA[0] * (1.0f / 1024.0f);
    float var = rB[0] * (1.0f / 1024.0f) - mu * mu;
    float rstd = rsqrtf(var + 1e-5f);

    const float4 gv = ((const float4*)g)[tid];
    const float4 bv = ((const float4*)bta)[tid];
    float4 o;
    o.x = (v0 - mu) * rstd * gv.x + bv.x;
    o.y = (v1 - mu) * rstd * gv.y + bv.y;
    o.z = (v2 - mu) * rstd * gv.z + bv.z;
    o.w = (v3 - mu) * rstd * gv.w + bv.w;
    ((float4*)(out + (size_t)r * DD))[tid] = o;
}

// ---------------- launch ----------------
extern "C" void kernel_launch(void* const* d_in, const int* in_sizes, int n_in,
                              void* d_out, int out_size) {
    (void)in_sizes; (void)n_in; (void)out_size;
    const int*   x    = (const int*)  d_in[0];
    const int*   sp   = (const int*)  d_in[1];
    const float* emb  = (const float*)d_in[2];
    const float* Wq   = (const float*)d_in[3];
    const float* bq   = (const float*)d_in[4];
    const float* Wk   = (const float*)d_in[5];
    const float* bk   = (const float*)d_in[6];
    const float* Wv   = (const float*)d_in[7];
    const float* bv   = (const float*)d_in[8];
    const float* Wo   = (const float*)d_in[9];
    const float* bo   = (const float*)d_in[10];
    const float* ln1g = (const float*)d_in[11];
    const float* ln1b = (const float*)d_in[12];
    const float* W1   = (const float*)d_in[13];
    const float* b1   = (const float*)d_in[14];
    const float* W2   = (const float*)d_in[15];
    const float* b2   = (const float*)d_in[16];
    const float* ln2g = (const float*)d_in[17];
    const float* ln2b = (const float*)d_in[18];
    const float* fcw  = (const float*)d_in[19];
    const float* fcb  = (const float*)d_in[20];
    float* out = (float*)d_out;

    float *h, *q, *k, *v, *attn, *tmp, *ffn, *scores;
    cudaGetSymbolAddress((void**)&h,      g_h);
    cudaGetSymbolAddress((void**)&q,      g_q);
    cudaGetSymbolAddress((void**)&k,      g_k);
    cudaGetSymbolAddress((void**)&v,      g_v);
    cudaGetSymbolAddress((void**)&attn,   g_attn);
    cudaGetSymbolAddress((void**)&tmp,    g_tmp);
    cudaGetSymbolAddress((void**)&ffn,    g_ffn);
    cudaGetSymbolAddress((void**)&scores, g_scores);

    dim3 thr(16, 16);

    embed_kernel<<<MTOK, 256>>>(x, emb, h);

    for (int l = 0; l < LL; l++) {
        const float* Wql = Wq + (size_t)l * DD * DD;
        const float* Wkl = Wk + (size_t)l * DD * DD;
        const float* Wvl = Wv + (size_t)l * DD * DD;
        const float* Wol = Wo + (size_t)l * DD * DD;
        const float* W1l = W1 + (size_t)l * DD * DFFN;
        const float* W2l = W2 + (size_t)l * DFFN * DD;

        gemm_tf32<<<dim3(MTOK/128, DD/128), 256>>>(h, Wql, bq + (size_t)l*DD, q,
            MTOK, DD, DD, DD, DD, DD, 0, (const int*)0);
        gemm_tf32<<<dim3(MTOK/128, DD/128), 256>>>(h, Wkl, bk + (size_t)l*DD, k,
            MTOK, DD, DD, DD, DD, DD, 0, (const int*)0);
        gemm_tf32<<<dim3(MTOK/128, DD/128), 256>>>(h, Wvl, bv + (size_t)l*DD, v,
            MTOK, DD, DD, DD, DD, DD, 0, (const int*)0);

        attn_scores<<<dim3(SS/64, SS/64, BB*HH), thr>>>(q, k, scores);
        softmax_kernel<<<BB*HH*SS, 256>>>(scores, sp);
        attn_pv<<<dim3(1, SS/64, BB*HH), thr>>>(scores, v, attn);

        gemm_tf32<<<dim3(MTOK/128, DD/128), 256>>>(attn, Wol, bo + (size_t)l*DD, tmp,
            MTOK, DD, DD, DD, DD, DD, 0, (const int*)0);
        add_ln<<<MTOK, 256>>>(h, tmp, ln1g + (size_t)l*DD, ln1b + (size_t)l*DD, h);

        gemm_tf32<<<dim3(MTOK/128, DFFN/128), 256>>>(h, W1l, b1 + (size_t)l*DFFN, ffn,
            MTOK, DFFN, DD, DD, DFFN, DFFN, 1, (const int*)0);
        gemm_tf32<<<dim3(MTOK/128, DD/128), 256>>>(ffn, W2l, b2 + (size_t)l*DD, tmp,
            MTOK, DD, DFFN, DFFN, DD, DD, 0, (const int*)0);
        add_ln<<<MTOK, 256>>>(h, tmp, ln2g + (size_t)l*DD, ln2b + (size_t)l*DD, h);
    }

    gemm_tf32<<<dim3(MTOK/128, OUTV/128), 256>>>(h, fcw, fcb, out,
        MTOK, OUTV, DD, DD, OUTV, OUTV, 2, sp);
}

// round 3
// speedup vs baseline: 3.7748x; 1.6944x over previous
#include <cuda_runtime.h>
#include <math.h>
#include <stddef.h>
#include <stdint.h>

#define BB   2
#define SS   1024
#define DD   1024
#define HH   16
#define DKK  64
#define LL   4
#define DFFN 4096
#define OUTV 32000
#define MTOK (BB*SS)

// ---------------- scratch (allocation-free: __device__ globals) ----------------
__device__ float g_h [MTOK*DD];
__device__ float g_ht[MTOK*DD];     // tf32-rounded copy of h for GEMM A input
__device__ float g_q [MTOK*DD];
__device__ float g_k [MTOK*DD];
__device__ float g_v [MTOK*DD];
__device__ float g_attn[MTOK*DD];
__device__ float g_tmp [MTOK*DD];
__device__ float g_ffn[(size_t)MTOK*DFFN];
__device__ float g_scores[(size_t)BB*HH*SS*SS];   // 128 MB

// ---------------- helpers ----------------
__device__ __forceinline__ float tf32r(float x) {
    uint32_t u;
    asm("cvt.rna.tf32.f32 %0, %1;" : "=r"(u) : "f"(x));
    return __uint_as_float(u);
}
__device__ __forceinline__ void mma_tf32(float* c, const uint32_t* a, const uint32_t* b) {
    asm volatile(
        "mma.sync.aligned.m16n8k8.row.col.f32.tf32.tf32.f32 "
        "{%0,%1,%2,%3}, {%4,%5,%6,%7}, {%8,%9}, {%0,%1,%2,%3};"
        : "+f"(c[0]), "+f"(c[1]), "+f"(c[2]), "+f"(c[3])
        : "r"(a[0]), "r"(a[1]), "r"(a[2]), "r"(a[3]), "r"(b[0]), "r"(b[1]));
}
__device__ __forceinline__ void cp16(uint32_t s, const void* g) {
    asm volatile("cp.async.cg.shared.global [%0], [%1], 16;" :: "r"(s), "l"(g));
}
#define CP_COMMIT() asm volatile("cp.async.commit_group;")
#define CP_WAIT1()  asm volatile("cp.async.wait_group 1;")

// ---------------- embedding (writes fp32 h and tf32-rounded ht) -----------------
__global__ void embed_kernel(const int* __restrict__ x, const float* __restrict__ emb,
                             float* __restrict__ h, float* __restrict__ ht) {
    int r = blockIdx.x;
    int tok = x[r];
    const float4* src = (const float4*)(emb + (size_t)tok * DD);
    float4 v = src[threadIdx.x];
    v.x *= 32.0f; v.y *= 32.0f; v.z *= 32.0f; v.w *= 32.0f;   // sqrt(1024)
    ((float4*)(h + (size_t)r * DD))[threadIdx.x] = v;
    float4 t = make_float4(tf32r(v.x), tf32r(v.y), tf32r(v.z), tf32r(v.w));
    ((float4*)(ht + (size_t)r * DD))[threadIdx.x] = t;
}

// =================================================================================
// Dense tf32 GEMM: 128x128x32 tiles, 3-stage cp.async, 8 warps (2x4), 64x32/warp.
// A pre-rounded to tf32; B (weights) cvt at fragment load.
// mode bit0: gelu, bit1: start_pos output mask, bit2: round output to tf32.
// blockIdx.z selects pointer set (QKV fusion).
// =================================================================================
#define AS_SZ (128*36)
#define BS_SZ (32*136)
#define GEMM_SMEM (3*(AS_SZ+BS_SZ)*4)

__global__ void __launch_bounds__(256,2) gemm_tc(
    const float* __restrict__ A,
    const float* __restrict__ B0, const float* __restrict__ bias0, float* __restrict__ C0,
    const float* __restrict__ B1, const float* __restrict__ bias1, float* __restrict__ C1,
    const float* __restrict__ B2, const float* __restrict__ bias2, float* __restrict__ C2,
    int K, int lda, int ldb, int ldc, int mode, const int* __restrict__ sp)
{
    const float* Bm = B0; const float* bias = bias0; float* C = C0;
    if (blockIdx.z == 1) { Bm = B1; bias = bias1; C = C1; }
    else if (blockIdx.z == 2) { Bm = B2; bias = bias2; C = C2; }

    extern __shared__ float sm[];
    float* As = sm;
    float* Bs = sm + 3*AS_SZ;

    int tid = threadIdx.x;
    int lane = tid & 31, warp = tid >> 5;
    int wm = warp >> 2, wn = warp & 3;
    int g = lane >> 2, tg = lane & 3;
    int row0 = blockIdx.x*128, col0 = blockIdx.y*128;

    const float* Abase = A + (size_t)row0 * lda;
    const float* Bbase = Bm + col0;

    int a_r = tid >> 3, a_c = (tid & 7) << 2;
    int b_r = tid >> 5, b_c = (tid & 31) << 2;
    uint32_t sA = (uint32_t)__cvta_generic_to_shared(As);
    uint32_t sB = (uint32_t)__cvta_generic_to_shared(Bs);

    int nch = K >> 5;

    // prologue: stages 0,1
    #pragma unroll
    for (int s = 0; s < 2; s++) {
        int k0 = s << 5;
        uint32_t dA = sA + (uint32_t)(s*AS_SZ) * 4;
        uint32_t dB = sB + (uint32_t)(s*BS_SZ) * 4;
        #pragma unroll
        for (int p = 0; p < 4; p++) {
            int r = a_r + 32*p;
            cp16(dA + (uint32_t)(r*36 + a_c)*4, Abase + (size_t)r*lda + k0 + a_c);
        }
        #pragma unroll
        for (int p = 0; p < 4; p++) {
            int r = b_r + 8*p;
            cp16(dB + (uint32_t)(r*136 + b_c)*4, Bbase + (size_t)(k0 + r)*ldb + b_c);
        }
        CP_COMMIT();
    }

    float acc[4][4][4] = {};

    for (int ch = 0; ch < nch; ch++) {
        CP_WAIT1();
        __syncthreads();
        if (ch + 2 < nch) {
            int s = (ch + 2) % 3, k0 = (ch + 2) << 5;
            uint32_t dA = sA + (uint32_t)(s*AS_SZ) * 4;
            uint32_t dB = sB + (uint32_t)(s*BS_SZ) * 4;
            #pragma unroll
            for (int p = 0; p < 4; p++) {
                int r = a_r + 32*p;
                cp16(dA + (uint32_t)(r*36 + a_c)*4, Abase + (size_t)r*lda + k0 + a_c);
            }
            #pragma unroll
            for (int p = 0; p < 4; p++) {
                int r = b_r + 8*p;
                cp16(dB + (uint32_t)(r*136 + b_c)*4, Bbase + (size_t)(k0 + r)*ldb + b_c);
            }
        }
        CP_COMMIT();

        const float* as = As + (ch % 3)*AS_SZ;
        const float* bs = Bs + (ch % 3)*BS_SZ;
        #pragma unroll
        for (int ks = 0; ks < 4; ks++) {
            int kc = ks << 3;
            uint32_t af[4][4], bf[4][2];
            #pragma unroll
            for (int m = 0; m < 4; m++) {
                const float* p = as + (wm*64 + m*16 + g)*36 + kc + tg;
                af[m][0] = __float_as_uint(p[0]);
                af[m][1] = __float_as_uint(p[8*36]);
                af[m][2] = __float_as_uint(p[4]);
                af[m][3] = __float_as_uint(p[8*36 + 4]);
            }
            #pragma unroll
            for (int n = 0; n < 4; n++) {
                const float* p = bs + (kc + tg)*136 + wn*32 + n*8 + g;
                bf[n][0] = __float_as_uint(tf32r(p[0]));
                bf[n][1] = __float_as_uint(tf32r(p[4*136]));
            }
            #pragma unroll
            for (int m = 0; m < 4; m++)
                #pragma unroll
                for (int n = 0; n < 4; n++)
                    mma_tf32(acc[m][n], af[m], bf[n]);
        }
    }

    // epilogue
    #pragma unroll
    for (int m = 0; m < 4; m++) {
        int r0 = row0 + wm*64 + m*16 + g;
        #pragma unroll
        for (int n = 0; n < 4; n++) {
            int c = col0 + wn*32 + n*8 + tg*2;
            float b0f = bias ? bias[c] : 0.0f;
            float b1f = bias ? bias[c + 1] : 0.0f;
            float v[4] = { acc[m][n][0] + b0f, acc[m][n][1] + b1f,
                           acc[m][n][2] + b0f, acc[m][n][3] + b1f };
            if (mode & 1) {
                #pragma unroll
                for (int i = 0; i < 4; i++)
                    v[i] = 0.5f * v[i] * (1.0f + erff(v[i] * 0.70710678118654752f));
            }
            if (mode & 2) {
                int r1 = r0 + 8;
                if ((r0 & 1023) < sp[r0 >> 10]) { v[0] = 0.0f; v[1] = 0.0f; }
                if ((r1 & 1023) < sp[r1 >> 10]) { v[2] = 0.0f; v[3] = 0.0f; }
            }
            if (mode & 4) {
                #pragma unroll
                for (int i = 0; i < 4; i++) v[i] = tf32r(v[i]);
            }
            *(float2*)&C[(size_t)r0 * ldc + c]       = make_float2(v[0], v[1]);
            *(float2*)&C[(size_t)(r0 + 8) * ldc + c] = make_float2(v[2], v[3]);
        }
    }
}

// =================================================================================
// Attention scores (NT): S[z,q,c] = sum_d Q[q,d]*K[c,d].  Inputs pre-rounded tf32.
// =================================================================================
#define SC_BS_SZ (128*36)
#define SC_SMEM (3*(AS_SZ+SC_BS_SZ)*4)

__global__ void __launch_bounds__(256,2) attn_scores_tc(
    const float* __restrict__ Q, const float* __restrict__ Kt, float* __restrict__ Sc)
{
    int z = blockIdx.z, bi = z >> 4, hi = z & 15;
    const float* Abase = Q + (size_t)bi*SS*DD + hi*DKK;
    const float* Bbase = Kt + (size_t)bi*SS*DD + hi*DKK;
    float* C = Sc + (size_t)z*SS*SS;

    extern __shared__ float sm[];
    float* As = sm;
    float* Bs = sm + 3*AS_SZ;

    int tid = threadIdx.x;
    int lane = tid & 31, warp = tid >> 5;
    int wm = warp >> 2, wn = warp & 3;
    int g = lane >> 2, tg = lane & 3;
    int row0 = blockIdx.x*128, col0 = blockIdx.y*128;

    int a_r = tid >> 3, a_c = (tid & 7) << 2;
    uint32_t sA = (uint32_t)__cvta_generic_to_shared(As);
    uint32_t sB = (uint32_t)__cvta_generic_to_shared(Bs);

    // K=64: exactly 2 chunks, both prefetched
    #pragma unroll
    for (int s = 0; s < 2; s++) {
        int k0 = s << 5;
        uint32_t dA = sA + (uint32_t)(s*AS_SZ) * 4;
        uint32_t dB = sB + (uint32_t)(s*SC_BS_SZ) * 4;
        #pragma unroll
        for (int p = 0; p < 4; p++) {
            int r = a_r + 32*p;
            cp16(dA + (uint32_t)(r*36 + a_c)*4, Abase + (size_t)(row0 + r)*DD + k0 + a_c);
            cp16(dB + (uint32_t)(r*36 + a_c)*4, Bbase + (size_t)(col0 + r)*DD + k0 + a_c);
        }
        CP_COMMIT();
    }

    float acc[4][4][4] = {};
    #pragma unroll
    for (int ch = 0; ch < 2; ch++) {
        CP_WAIT1();
        __syncthreads();
        CP_COMMIT();   // keep group count advancing
        const float* as = As + ch*AS_SZ;
        const float* bs = Bs + ch*SC_BS_SZ;
        #pragma unroll
        for (int ks = 0; ks < 4; ks++) {
            int kc = ks << 3;
            uint32_t af[4][4], bf[4][2];
            #pragma unroll
            for (int m = 0; m < 4; m++) {
                const float* p = as + (wm*64 + m*16 + g)*36 + kc + tg;
                af[m][0] = __float_as_uint(p[0]);
                af[m][1] = __float_as_uint(p[8*36]);
                af[m][2] = __float_as_uint(p[4]);
                af[m][3] = __float_as_uint(p[8*36 + 4]);
            }
            #pragma unroll
            for (int n = 0; n < 4; n++) {
                const float* p = bs + (wn*32 + n*8 + g)*36 + kc + tg;
                bf[n][0] = __float_as_uint(p[0]);
                bf[n][1] = __float_as_uint(p[4]);
            }
            #pragma unroll
            for (int m = 0; m < 4; m++)
                #pragma unroll
                for (int n = 0; n < 4; n++)
                    mma_tf32(acc[m][n], af[m], bf[n]);
        }
    }

    #pragma unroll
    for (int m = 0; m < 4; m++) {
        int r0 = row0 + wm*64 + m*16 + g;
        #pragma unroll
        for (int n = 0; n < 4; n++) {
            int c = col0 + wn*32 + n*8 + tg*2;
            *(float2*)&C[(size_t)r0 * SS + c]       = make_float2(acc[m][n][0], acc[m][n][1]);
            *(float2*)&C[(size_t)(r0 + 8) * SS + c] = make_float2(acc[m][n][2], acc[m][n][3]);
        }
    }
}

// =================================================================================
// PV: O[z,q,d] = sum_c P[q,c]*V[c,d].  128x64x32 tiles, 8 warps (4x2), 32x32/warp.
// Output rounded to tf32 (feeds Wo GEMM as A).
// =================================================================================
#define PV_BS_SZ (32*72)
#define PV_SMEM (3*(AS_SZ+PV_BS_SZ)*4)

__global__ void __launch_bounds__(256,2) attn_pv_tc(
    const float* __restrict__ P, const float* __restrict__ V, float* __restrict__ O)
{
    int z = blockIdx.z, bi = z >> 4, hi = z & 15;
    const float* Abase = P + (size_t)z*SS*SS;
    const float* Bbase = V + (size_t)bi*SS*DD + hi*DKK;
    float* C = O + (size_t)bi*SS*DD + hi*DKK;

    extern __shared__ float sm[];
    float* As = sm;
    float* Bs = sm + 3*AS_SZ;

    int tid = threadIdx.x;
    int lane = tid & 31, warp = tid >> 5;
    int wm = warp >> 1, wn = warp & 1;        // 4 x 2 warps, 32x32 each
    int g = lane >> 2, tg = lane & 3;
    int row0 = blockIdx.x*128;

    int a_r = tid >> 3, a_c = (tid & 7) << 2;
    int b_r = tid >> 4, b_c = (tid & 15) << 2;
    uint32_t sA = (uint32_t)__cvta_generic_to_shared(As);
    uint32_t sB = (uint32_t)__cvta_generic_to_shared(Bs);

    #pragma unroll
    for (int s = 0; s < 2; s++) {
        int k0 = s << 5;
        uint32_t dA = sA + (uint32_t)(s*AS_SZ) * 4;
        uint32_t dB = sB + (uint32_t)(s*PV_BS_SZ) * 4;
        #pragma unroll
        for (int p = 0; p < 4; p++) {
            int r = a_r + 32*p;
            cp16(dA + (uint32_t)(r*36 + a_c)*4, Abase + (size_t)(row0 + r)*SS + k0 + a_c);
        }
        #pragma unroll
        for (int p = 0; p < 2; p++) {
            int r = b_r + 16*p;
            cp16(dB + (uint32_t)(r*72 + b_c)*4, Bbase + (size_t)(k0 + r)*DD + b_c);
        }
        CP_COMMIT();
    }

    float acc[2][4][4] = {};
    int nch = SS >> 5;     // 32
    for (int ch = 0; ch < nch; ch++) {
        CP_WAIT1();
        __syncthreads();
        if (ch + 2 < nch) {
            int s = (ch + 2) % 3, k0 = (ch + 2) << 5;
            uint32_t dA = sA + (uint32_t)(s*AS_SZ) * 4;
            uint32_t dB = sB + (uint32_t)(s*PV_BS_SZ) * 4;
            #pragma unroll
            for (int p = 0; p < 4; p++) {
                int r = a_r + 32*p;
                cp16(dA + (uint32_t)(r*36 + a_c)*4, Abase + (size_t)(row0 + r)*SS + k0 + a_c);
            }
            #pragma unroll
            for (int p = 0; p < 2; p++) {
                int r = b_r + 16*p;
                cp16(dB + (uint32_t)(r*72 + b_c)*4, Bbase + (size_t)(k0 + r)*DD + b_c);
            }
        }
        CP_COMMIT();

        const float* as = As + (ch % 3)*AS_SZ;
        const float* bs = Bs + (ch % 3)*PV_BS_SZ;
        #pragma unroll
        for (int ks = 0; ks < 4; ks++) {
            int kc = ks << 3;
            uint32_t af[2][4], bf[4][2];
            #pragma unroll
            for (int m = 0; m < 2; m++) {
                const float* p = as + (wm*32 + m*16 + g)*36 + kc + tg;
                af[m][0] = __float_as_uint(p[0]);
                af[m][1] = __float_as_uint(p[8*36]);
                af[m][2] = __float_as_uint(p[4]);
                af[m][3] = __float_as_uint(p[8*36 + 4]);
            }
            #pragma unroll
            for (int n = 0; n < 4; n++) {
                const float* p = bs + (kc + tg)*72 + wn*32 + n*8 + g;
                bf[n][0] = __float_as_uint(p[0]);
                bf[n][1] = __float_as_uint(p[4*72]);
            }
            #pragma unroll
            for (int m = 0; m < 2; m++)
                #pragma unroll
                for (int n = 0; n < 4; n++)
                    mma_tf32(acc[m][n], af[m], bf[n]);
        }
    }

    #pragma unroll
    for (int m = 0; m < 2; m++) {
        int r0 = row0 + wm*32 + m*16 + g;
        #pragma unroll
        for (int n = 0; n < 4; n++) {
            int c = wn*32 + n*8 + tg*2;
            *(float2*)&C[(size_t)r0 * DD + c] =
                make_float2(tf32r(acc[m][n][0]), tf32r(acc[m][n][1]));
            *(float2*)&C[(size_t)(r0 + 8) * DD + c] =
                make_float2(tf32r(acc[m][n][2]), tf32r(acc[m][n][3]));
        }
    }
}

// ---------------- softmax: scale + alibi + mask, in place, rounds probs ---------
__global__ void __launch_bounds__(256) softmax_kernel(
    float* __restrict__ Sc, const int* __restrict__ sp)
{
    int gid = blockIdx.x;           // z*S + q
    int q = gid & (SS - 1);
    int z = gid >> 10;
    int hi = z & 15, bi = z >> 4;
    float* row = Sc + (size_t)gid * SS;
    int spv = sp[bi];
    float slope = exp2f(-0.5f * (float)(hi + 1));
    int tid = threadIdx.x;

    float vals[4];
    float mx = -1e30f;
    #pragma unroll
    for (int i = 0; i < 4; i++) {
        int c = tid + i * 256;
        float v = row[c] * 0.125f + slope * (float)(c - q);
        bool ok = (q >= c) || (q < spv) || (c < spv);
        v = ok ? v : -1e9f;
        vals[i] = v;
        mx = fmaxf(mx, v);
    }
    __shared__ float red[256];
    red[tid] = mx; __syncthreads();
    for (int s = 128; s > 0; s >>= 1) {
        if (tid < s) red[tid] = fmaxf(red[tid], red[tid + s]);
        __syncthreads();
    }
    mx = red[0]; __syncthreads();

    float sum = 0.0f;
    #pragma unroll
    for (int i = 0; i < 4; i++) { vals[i] = expf(vals[i] - mx); sum += vals[i]; }
    red[tid] = sum; __syncthreads();
    for (int s = 128; s > 0; s >>= 1) {
        if (tid < s) red[tid] += red[tid + s];
        __syncthreads();
    }
    float inv = 1.0f / red[0];
    #pragma unroll
    for (int i = 0; i < 4; i++) row[tid + i * 256] = tf32r(vals[i] * inv);
}

// ---------------- residual add + layernorm; writes fp32 out + tf32 out_t --------
__global__ void __launch_bounds__(256) add_ln(
    const float* __restrict__ X, const float* __restrict__ Rs,
    const float* __restrict__ g, const float* __restrict__ bta,
    float* __restrict__ out, float* __restrict__ out_t)
{
    int r = blockIdx.x, tid = threadIdx.x;
    const float4* x4 = (const float4*)(X + (size_t)r * DD);
    const float4* r4 = (const float4*)(Rs + (size_t)r * DD);
    float4 xv = x4[tid], rv = r4[tid];
    float v0 = xv.x + rv.x, v1 = xv.y + rv.y, v2 = xv.z + rv.z, v3 = xv.w + rv.w;
    float s1 = v0 + v1 + v2 + v3;
    float s2 = v0*v0 + v1*v1 + v2*v2 + v3*v3;

    __shared__ float rA[256], rB[256];
    rA[tid] = s1; rB[tid] = s2; __syncthreads();
    for (int s = 128; s > 0; s >>= 1) {
        if (tid < s) { rA[tid] += rA[tid + s]; rB[tid] += rB[tid + s]; }
        __syncthreads();
    }
    float mu = rA[0] * (1.0f / 1024.0f);
    float var = rB[0] * (1.0f / 1024.0f) - mu * mu;
    float rstd = rsqrtf(var + 1e-5f);

    const float4 gv = ((const float4*)g)[tid];
    const float4 bv = ((const float4*)bta)[tid];
    float4 o;
    o.x = (v0 - mu) * rstd * gv.x + bv.x;
    o.y = (v1 - mu) * rstd * gv.y + bv.y;
    o.z = (v2 - mu) * rstd * gv.z + bv.z;
    o.w = (v3 - mu) * rstd * gv.w + bv.w;
    ((float4*)(out + (size_t)r * DD))[tid] = o;
    float4 t = make_float4(tf32r(o.x), tf32r(o.y), tf32r(o.z), tf32r(o.w));
    ((float4*)(out_t + (size_t)r * DD))[tid] = t;
}

// ---------------- launch ----------------
extern "C" void kernel_launch(void* const* d_in, const int* in_sizes, int n_in,
                              void* d_out, int out_size) {
    (void)in_sizes; (void)n_in; (void)out_size;
    const int*   x    = (const int*)  d_in[0];
    const int*   sp   = (const int*)  d_in[1];
    const float* emb  = (const float*)d_in[2];
    const float* Wq   = (const float*)d_in[3];
    const float* bq   = (const float*)d_in[4];
    const float* Wk   = (const float*)d_in[5];
    const float* bk   = (const float*)d_in[6];
    const float* Wv   = (const float*)d_in[7];
    const float* bv   = (const float*)d_in[8];
    const float* Wo   = (const float*)d_in[9];
    const float* bo   = (const float*)d_in[10];
    const float* ln1g = (const float*)d_in[11];
    const float* ln1b = (const float*)d_in[12];
    const float* W1   = (const float*)d_in[13];
    const float* b1   = (const float*)d_in[14];
    const float* W2   = (const float*)d_in[15];
    const float* b2   = (const float*)d_in[16];
    const float* ln2g = (const float*)d_in[17];
    const float* ln2b = (const float*)d_in[18];
    const float* fcw  = (const float*)d_in[19];
    const float* fcb  = (const float*)d_in[20];
    float* out = (float*)d_out;

    float *h, *ht, *q, *k, *v, *attn, *tmp, *ffn, *scores;
    cudaGetSymbolAddress((void**)&h,      g_h);
    cudaGetSymbolAddress((void**)&ht,     g_ht);
    cudaGetSymbolAddress((void**)&q,      g_q);
    cudaGetSymbolAddress((void**)&k,      g_k);
    cudaGetSymbolAddress((void**)&v,      g_v);
    cudaGetSymbolAddress((void**)&attn,   g_attn);
    cudaGetSymbolAddress((void**)&tmp,    g_tmp);
    cudaGetSymbolAddress((void**)&ffn,    g_ffn);
    cudaGetSymbolAddress((void**)&scores, g_scores);

    static int attr_done = 0;
    if (!attr_done) {
        cudaFuncSetAttribute(gemm_tc,        cudaFuncAttributeMaxDynamicSharedMemorySize, GEMM_SMEM);
        cudaFuncSetAttribute(attn_scores_tc, cudaFuncAttributeMaxDynamicSharedMemorySize, SC_SMEM);
        cudaFuncSetAttribute(attn_pv_tc,     cudaFuncAttributeMaxDynamicSharedMemorySize, PV_SMEM);
        attr_done = 1;
    }

    embed_kernel<<<MTOK, 256>>>(x, emb, h, ht);

    for (int l = 0; l < LL; l++) {
        const float* Wql = Wq + (size_t)l * DD * DD;
        const float* Wkl = Wk + (size_t)l * DD * DD;
        const float* Wvl = Wv + (size_t)l * DD * DD;
        const float* Wol = Wo + (size_t)l * DD * DD;
        const float* W1l = W1 + (size_t)l * DD * DFFN;
        const float* W2l = W2 + (size_t)l * DFFN * DD;

        // fused QKV (rounded outputs)
        gemm_tc<<<dim3(MTOK/128, DD/128, 3), 256, GEMM_SMEM>>>(
            ht,
            Wql, bq + (size_t)l*DD, q,
            Wkl, bk + (size_t)l*DD, k,
            Wvl, bv + (size_t)l*DD, v,
            DD, DD, DD, DD, 4, (const int*)0);

        attn_scores_tc<<<dim3(SS/128, SS/128, BB*HH), 256, SC_SMEM>>>(q, k, scores);
        softmax_kernel<<<BB*HH*SS, 256>>>(scores, sp);
        attn_pv_tc<<<dim3(SS/128, 1, BB*HH), 256, PV_SMEM>>>(scores, v, attn);

        gemm_tc<<<dim3(MTOK/128, DD/128, 1), 256, GEMM_SMEM>>>(
            attn, Wol, bo + (size_t)l*DD, tmp,
            (const float*)0, (const float*)0, (float*)0,
            (const float*)0, (const float*)0, (float*)0,
            DD, DD, DD, DD, 0, (const int*)0);
        add_ln<<<MTOK, 256>>>(h, tmp, ln1g + (size_t)l*DD, ln1b + (size_t)l*DD, h, ht);

        gemm_tc<<<dim3(MTOK/128, DFFN/128, 1), 256, GEMM_SMEM>>>(
            ht, W1l, b1 + (size_t)l*DFFN, ffn,
            (const float*)0, (const float*)0, (float*)0,
            (const float*)0, (const float*)0, (float*)0,
            DD, DD, DFFN, DFFN, 1 | 4, (const int*)0);
        gemm_tc<<<dim3(MTOK/128, DD/128, 1), 256, GEMM_SMEM>>>(
            ffn, W2l, b2 + (size_t)l*DD, tmp,
            (const float*)0, (const float*)0, (float*)0,
            (const float*)0, (const float*)0, (float*)0,
            DFFN, DFFN, DD, DD, 0, (const int*)0);
        add_ln<<<MTOK, 256>>>(h, tmp, ln2g + (size_t)l*DD, ln2b + (size_t)l*DD, h, ht);
    }

    gemm_tc<<<dim3(MTOK/128, OUTV/128, 1), 256, GEMM_SMEM>>>(
        ht, fcw, fcb, out,
        (const float*)0, (const float*)0, (float*)0,
        (const float*)0, (const float*)0, (float*)0,
        DD, DD, OUTV, OUTV, 2, sp);
}

// round 4
// speedup vs baseline: 4.0600x; 1.0755x over previous
#include <cuda_runtime.h>
#include <math.h>
#include <stddef.h>
#include <stdint.h>

#define BB   2
#define SS   1024
#define DD   1024
#define HH   16
#define DKK  64
#define LL   4
#define DFFN 4096
#define OUTV 32000
#define MTOK (BB*SS)

// ---------------- scratch (allocation-free: __device__ globals) ----------------
__device__ float g_h [MTOK*DD];
__device__ float g_ht[MTOK*DD];     // tf32-rounded copy of h for GEMM A input
__device__ float g_q [MTOK*DD];
__device__ float g_k [MTOK*DD];
__device__ float g_v [MTOK*DD];
__device__ float g_attn[MTOK*DD];
__device__ float g_tmp [MTOK*DD];
__device__ float g_ffn[(size_t)MTOK*DFFN];

// ---------------- helpers ----------------
__device__ __forceinline__ float tf32r(float x) {
    uint32_t u;
    asm("cvt.rna.tf32.f32 %0, %1;" : "=r"(u) : "f"(x));
    return __uint_as_float(u);
}
__device__ __forceinline__ void mma_tf32(float* c, const uint32_t* a, const uint32_t* b) {
    asm volatile(
        "mma.sync.aligned.m16n8k8.row.col.f32.tf32.tf32.f32 "
        "{%0,%1,%2,%3}, {%4,%5,%6,%7}, {%8,%9}, {%0,%1,%2,%3};"
        : "+f"(c[0]), "+f"(c[1]), "+f"(c[2]), "+f"(c[3])
        : "r"(a[0]), "r"(a[1]), "r"(a[2]), "r"(a[3]), "r"(b[0]), "r"(b[1]));
}
__device__ __forceinline__ void cp16(uint32_t s, const void* g) {
    asm volatile("cp.async.cg.shared.global [%0], [%1], 16;" :: "r"(s), "l"(g));
}
#define CP_COMMIT() asm volatile("cp.async.commit_group;")
#define CP_WAIT1()  asm volatile("cp.async.wait_group 1;")

// ---------------- embedding (writes fp32 h and tf32-rounded ht) -----------------
__global__ void embed_kernel(const int* __restrict__ x, const float* __restrict__ emb,
                             float* __restrict__ h, float* __restrict__ ht) {
    int r = blockIdx.x;
    int tok = x[r];
    const float4* src = (const float4*)(emb + (size_t)tok * DD);
    float4 v = src[threadIdx.x];
    v.x *= 32.0f; v.y *= 32.0f; v.z *= 32.0f; v.w *= 32.0f;   // sqrt(1024)
    ((float4*)(h + (size_t)r * DD))[threadIdx.x] = v;
    float4 t = make_float4(tf32r(v.x), tf32r(v.y), tf32r(v.z), tf32r(v.w));
    ((float4*)(ht + (size_t)r * DD))[threadIdx.x] = t;
}

// =================================================================================
// Dense tf32 GEMM: 128x128x32 tiles, 3-stage cp.async, 8 warps (2x4), 64x32/warp.
// =================================================================================
#define AS_SZ (128*36)
#define BS_SZ (32*136)
#define GEMM_SMEM (3*(AS_SZ+BS_SZ)*4)

__global__ void __launch_bounds__(256,2) gemm_tc(
    const float* __restrict__ A,
    const float* __restrict__ B0, const float* __restrict__ bias0, float* __restrict__ C0,
    const float* __restrict__ B1, const float* __restrict__ bias1, float* __restrict__ C1,
    const float* __restrict__ B2, const float* __restrict__ bias2, float* __restrict__ C2,
    int K, int lda, int ldb, int ldc, int mode, const int* __restrict__ sp)
{
    const float* Bm = B0; const float* bias = bias0; float* C = C0;
    if (blockIdx.z == 1) { Bm = B1; bias = bias1; C = C1; }
    else if (blockIdx.z == 2) { Bm = B2; bias = bias2; C = C2; }

    extern __shared__ float sm[];
    float* As = sm;
    float* Bs = sm + 3*AS_SZ;

    int tid = threadIdx.x;
    int lane = tid & 31, warp = tid >> 5;
    int wm = warp >> 2, wn = warp & 3;
    int g = lane >> 2, tg = lane & 3;
    int row0 = blockIdx.x*128, col0 = blockIdx.y*128;

    const float* Abase = A + (size_t)row0 * lda;
    const float* Bbase = Bm + col0;

    int a_r = tid >> 3, a_c = (tid & 7) << 2;
    int b_r = tid >> 5, b_c = (tid & 31) << 2;
    uint32_t sA = (uint32_t)__cvta_generic_to_shared(As);
    uint32_t sB = (uint32_t)__cvta_generic_to_shared(Bs);

    int nch = K >> 5;

    #pragma unroll
    for (int s = 0; s < 2; s++) {
        int k0 = s << 5;
        uint32_t dA = sA + (uint32_t)(s*AS_SZ) * 4;
        uint32_t dB = sB + (uint32_t)(s*BS_SZ) * 4;
        #pragma unroll
        for (int p = 0; p < 4; p++) {
            int r = a_r + 32*p;
            cp16(dA + (uint32_t)(r*36 + a_c)*4, Abase + (size_t)r*lda + k0 + a_c);
        }
        #pragma unroll
        for (int p = 0; p < 4; p++) {
            int r = b_r + 8*p;
            cp16(dB + (uint32_t)(r*136 + b_c)*4, Bbase + (size_t)(k0 + r)*ldb + b_c);
        }
        CP_COMMIT();
    }

    float acc[4][4][4] = {};

    for (int ch = 0; ch < nch; ch++) {
        CP_WAIT1();
        __syncthreads();
        if (ch + 2 < nch) {
            int s = (ch + 2) % 3, k0 = (ch + 2) << 5;
            uint32_t dA = sA + (uint32_t)(s*AS_SZ) * 4;
            uint32_t dB = sB + (uint32_t)(s*BS_SZ) * 4;
            #pragma unroll
            for (int p = 0; p < 4; p++) {
                int r = a_r + 32*p;
                cp16(dA + (uint32_t)(r*36 + a_c)*4, Abase + (size_t)r*lda + k0 + a_c);
            }
            #pragma unroll
            for (int p = 0; p < 4; p++) {
                int r = b_r + 8*p;
                cp16(dB + (uint32_t)(r*136 + b_c)*4, Bbase + (size_t)(k0 + r)*ldb + b_c);
            }
        }
        CP_COMMIT();

        const float* as = As + (ch % 3)*AS_SZ;
        const float* bs = Bs + (ch % 3)*BS_SZ;
        #pragma unroll
        for (int ks = 0; ks < 4; ks++) {
            int kc = ks << 3;
            uint32_t af[4][4], bf[4][2];
            #pragma unroll
            for (int m = 0; m < 4; m++) {
                const float* p = as + (wm*64 + m*16 + g)*36 + kc + tg;
                af[m][0] = __float_as_uint(p[0]);
                af[m][1] = __float_as_uint(p[8*36]);
                af[m][2] = __float_as_uint(p[4]);
                af[m][3] = __float_as_uint(p[8*36 + 4]);
            }
            #pragma unroll
            for (int n = 0; n < 4; n++) {
                const float* p = bs + (kc + tg)*136 + wn*32 + n*8 + g;
                bf[n][0] = __float_as_uint(tf32r(p[0]));
                bf[n][1] = __float_as_uint(tf32r(p[4*136]));
            }
            #pragma unroll
            for (int m = 0; m < 4; m++)
                #pragma unroll
                for (int n = 0; n < 4; n++)
                    mma_tf32(acc[m][n], af[m], bf[n]);
        }
    }

    #pragma unroll
    for (int m = 0; m < 4; m++) {
        int r0 = row0 + wm*64 + m*16 + g;
        #pragma unroll
        for (int n = 0; n < 4; n++) {
            int c = col0 + wn*32 + n*8 + tg*2;
            float b0f = bias ? bias[c] : 0.0f;
            float b1f = bias ? bias[c + 1] : 0.0f;
            float v[4] = { acc[m][n][0] + b0f, acc[m][n][1] + b1f,
                           acc[m][n][2] + b0f, acc[m][n][3] + b1f };
            if (mode & 1) {
                #pragma unroll
                for (int i = 0; i < 4; i++)
                    v[i] = 0.5f * v[i] * (1.0f + erff(v[i] * 0.70710678118654752f));
            }
            if (mode & 2) {
                int r1 = r0 + 8;
                if ((r0 & 1023) < sp[r0 >> 10]) { v[0] = 0.0f; v[1] = 0.0f; }
                if ((r1 & 1023) < sp[r1 >> 10]) { v[2] = 0.0f; v[3] = 0.0f; }
            }
            if (mode & 4) {
                #pragma unroll
                for (int i = 0; i < 4; i++) v[i] = tf32r(v[i]);
            }
            *(float2*)&C[(size_t)r0 * ldc + c]       = make_float2(v[0], v[1]);
            *(float2*)&C[(size_t)(r0 + 8) * ldc + c] = make_float2(v[2], v[3]);
        }
    }
}

// =================================================================================
// Flash attention: per (z, 128-row q-tile), loop over 128-col K/V tiles.
// 8 warps; warp w owns q-rows [w*16, w*16+16). Online softmax, quad-shfl
// reductions only. P goes through per-warp SMEM region (C-frag -> A-frag).
// Q/K/V already tf32-rounded. Output tf32-rounded.
// =================================================================================
#define FA_LDK 72
#define FA_LDP 132
#define FA_KV (128*FA_LDK)
#define FA_SMEM ((4*FA_KV + 128*FA_LDP)*4)

__global__ void __launch_bounds__(256,1) flash_attn(
    const float* __restrict__ Q, const float* __restrict__ Kg,
    const float* __restrict__ Vg, float* __restrict__ O,
    const int* __restrict__ sp)
{
    int z = blockIdx.z, bi = z >> 4, hi = z & 15;
    int q0 = blockIdx.x * 128;
    const float* Qb = Q  + (size_t)bi*SS*DD + hi*DKK;
    const float* Kb = Kg + (size_t)bi*SS*DD + hi*DKK;
    const float* Vb = Vg + (size_t)bi*SS*DD + hi*DKK;
    float* Ob = O + (size_t)bi*SS*DD + hi*DKK;

    extern __shared__ float sm[];
    float* Ks = sm;                    // [2][128][72]
    float* Vs = sm + 2*FA_KV;          // [2][128][72]
    float* Ps = sm + 4*FA_KV;          // [128][132]; doubles as Q staging
    uint32_t sBase = (uint32_t)__cvta_generic_to_shared(sm);

    int tid = threadIdx.x;
    int lane = tid & 31, warp = tid >> 5;
    int g = lane >> 2, tg = lane & 3;
    int wq = warp * 16;
    int spv = sp[bi];
    float slope = exp2f(-0.5f * (float)(hi + 1));

    // ---- stage Q tile, pull per-warp Q fragments into registers ----
    #pragma unroll
    for (int p = 0; p < 8; p++) {
        int i = tid + (p << 8);
        int r = i >> 4, c = (i & 15) << 2;
        *(float4*)&Ps[r*FA_LDK + c] = *(const float4*)(Qb + (size_t)(q0 + r)*DD + c);
    }
    __syncthreads();
    uint32_t aq[8][4];
    #pragma unroll
    for (int kf = 0; kf < 8; kf++) {
        const float* p = Ps + (wq + g)*FA_LDK + kf*8 + tg;
        aq[kf][0] = __float_as_uint(p[0]);
        aq[kf][1] = __float_as_uint(p[8*FA_LDK]);
        aq[kf][2] = __float_as_uint(p[4]);
        aq[kf][3] = __float_as_uint(p[8*FA_LDK + 4]);
    }
    __syncthreads();   // Ps now free for P

    int nt = (q0 >= 256) ? (q0 >> 7) + 1 : 8;

    // ---- prologue: tile 0 into stage 0 ----
    {
        const float* Kt = Kb; const float* Vt = Vb;
        #pragma unroll
        for (int p = 0; p < 8; p++) {
            int i = tid + (p << 8);
            int r = i >> 4, c = (i & 15) << 2;
            cp16(sBase + (uint32_t)(r*FA_LDK + c)*4,            Kt + (size_t)r*DD + c);
            cp16(sBase + (uint32_t)(2*FA_KV + r*FA_LDK + c)*4,  Vt + (size_t)r*DD + c);
        }
        CP_COMMIT();
    }

    float m_i[2] = {-1e30f, -1e30f};
    float l_i[2] = {0.0f, 0.0f};
    float acc_o[8][4] = {};
    float* Pw = Ps + wq*FA_LDP;        // warp-private 16x128 P region

    for (int t = 0; t < nt; t++) {
        __syncthreads();               // stage (t+1)&1 free of old readers
        if (t + 1 < nt) {
            int st = (t + 1) & 1;
            const float* Kt = Kb + (size_t)((t+1) << 7)*DD;
            const float* Vt = Vb + (size_t)((t+1) << 7)*DD;
            #pragma unroll
            for (int p = 0; p < 8; p++) {
                int i = tid + (p << 8);
                int r = i >> 4, c = (i & 15) << 2;
                cp16(sBase + (uint32_t)(st*FA_KV + r*FA_LDK + c)*4,     Kt + (size_t)r*DD + c);
                cp16(sBase + (uint32_t)((2+st)*FA_KV + r*FA_LDK + c)*4, Vt + (size_t)r*DD + c);
            }
        }
        CP_COMMIT();
        CP_WAIT1();
        __syncthreads();               // tile t data visible to all

        const float* ks = Ks + (t & 1)*FA_KV;
        const float* vs = Vs + (t & 1)*FA_KV;

        // ---- S = Q K^T : acc_s[16][4] (16 rows x 128 cols per warp) ----
        float acc_s[16][4] = {};
        #pragma unroll
        for (int kf = 0; kf < 8; kf++) {
            int kc = kf << 3;
            #pragma unroll
            for (int nf = 0; nf < 16; nf++) {
                uint32_t bf[2];
                const float* p = ks + (nf*8 + g)*FA_LDK + kc + tg;
                bf[0] = __float_as_uint(p[0]);
                bf[1] = __float_as_uint(p[4]);
                mma_tf32(acc_s[nf], aq[kf], bf);
            }
        }

        // ---- scale + alibi + mask, row max ----
        int c0 = t << 7;
        int qr0 = q0 + wq + g, qr1 = qr0 + 8;
        float tm0 = -1e30f, tm1 = -1e30f;
        #pragma unroll
        for (int nf = 0; nf < 16; nf++) {
            int c = c0 + nf*8 + tg*2;
            #pragma unroll
            for (int j = 0; j < 2; j++) {
                int cc = c + j;
                float s0 = acc_s[nf][j]   * 0.125f + slope * (float)(cc - qr0);
                float s1 = acc_s[nf][j+2] * 0.125f + slope * (float)(cc - qr1);
                bool ok0 = (qr0 >= cc) || (qr0 < spv) || (cc < spv);
                bool ok1 = (qr1 >= cc) || (qr1 < spv) || (cc < spv);
                acc_s[nf][j]   = ok0 ? s0 : -1e9f;
                acc_s[nf][j+2] = ok1 ? s1 : -1e9f;
                tm0 = fmaxf(tm0, acc_s[nf][j]);
                tm1 = fmaxf(tm1, acc_s[nf][j+2]);
            }
        }
        tm0 = fmaxf(tm0, __shfl_xor_sync(0xffffffffu, tm0, 1));
        tm0 = fmaxf(tm0, __shfl_xor_sync(0xffffffffu, tm0, 2));
        tm1 = fmaxf(tm1, __shfl_xor_sync(0xffffffffu, tm1, 1));
        tm1 = fmaxf(tm1, __shfl_xor_sync(0xffffffffu, tm1, 2));

        float mn0 = fmaxf(m_i[0], tm0), mn1 = fmaxf(m_i[1], tm1);
        float al0 = expf(m_i[0] - mn0),  al1 = expf(m_i[1] - mn1);
        m_i[0] = mn0; m_i[1] = mn1;

        // ---- p = exp(s - m), row sums, write P (tf32) to warp SMEM ----
        float rs0 = 0.0f, rs1 = 0.0f;
        #pragma unroll
        for (int nf = 0; nf < 16; nf++) {
            float p0 = expf(acc_s[nf][0] - mn0);
            float p1 = expf(acc_s[nf][1] - mn0);
            float p2 = expf(acc_s[nf][2] - mn1);
            float p3 = expf(acc_s[nf][3] - mn1);
            rs0 += p0 + p1; rs1 += p2 + p3;
            int col = nf*8 + tg*2;
            *(float2*)&Pw[g*FA_LDP + col]       = make_float2(tf32r(p0), tf32r(p1));
            *(float2*)&Pw[(g+8)*FA_LDP + col]   = make_float2(tf32r(p2), tf32r(p3));
        }
        rs0 += __shfl_xor_sync(0xffffffffu, rs0, 1);
        rs0 += __shfl_xor_sync(0xffffffffu, rs0, 2);
        rs1 += __shfl_xor_sync(0xffffffffu, rs1, 1);
        rs1 += __shfl_xor_sync(0xffffffffu, rs1, 2);
        l_i[0] = l_i[0]*al0 + rs0;
        l_i[1] = l_i[1]*al1 + rs1;

        #pragma unroll
        for (int nf = 0; nf < 8; nf++) {
            acc_o[nf][0] *= al0; acc_o[nf][1] *= al0;
            acc_o[nf][2] *= al1; acc_o[nf][3] *= al1;
        }
        __syncwarp();

        // ---- O += P V ----
        #pragma unroll
        for (int kf = 0; kf < 16; kf++) {
            int kc = kf << 3;
            uint32_t af[4];
            const float* p = Pw + g*FA_LDP + kc + tg;
            af[0] = __float_as_uint(p[0]);
            af[1] = __float_as_uint(p[8*FA_LDP]);
            af[2] = __float_as_uint(p[4]);
            af[3] = __float_as_uint(p[8*FA_LDP + 4]);
            #pragma unroll
            for (int nf = 0; nf < 8; nf++) {
                uint32_t bf[2];
                const float* q2 = vs + (kc + tg)*FA_LDK + nf*8 + g;
                bf[0] = __float_as_uint(q2[0]);
                bf[1] = __float_as_uint(q2[4*FA_LDK]);
                mma_tf32(acc_o[nf], af, bf);
            }
        }
        __syncwarp();
    }

    // ---- finalize: divide by l, write tf32-rounded O ----
    float inv0 = 1.0f / l_i[0], inv1 = 1.0f / l_i[1];
    int qr0 = q0 + wq + g;
    #pragma unroll
    for (int nf = 0; nf < 8; nf++) {
        int c = nf*8 + tg*2;
        *(float2*)&Ob[(size_t)qr0*DD + c] =
            make_float2(tf32r(acc_o[nf][0]*inv0), tf32r(acc_o[nf][1]*inv0));
        *(float2*)&Ob[(size_t)(qr0+8)*DD + c] =
            make_float2(tf32r(acc_o[nf][2]*inv1), tf32r(acc_o[nf][3]*inv1));
    }
}

// ---------------- residual add + layernorm; writes fp32 out + tf32 out_t --------
__global__ void __launch_bounds__(256) add_ln(
    const float* __restrict__ X, const float* __restrict__ Rs,
    const float* __restrict__ g, const float* __restrict__ bta,
    float* __restrict__ out, float* __restrict__ out_t)
{
    int r = blockIdx.x, tid = threadIdx.x;
    const float4* x4 = (const float4*)(X + (size_t)r * DD);
    const float4* r4 = (const float4*)(Rs + (size_t)r * DD);
    float4 xv = x4[tid], rv = r4[tid];
    float v0 = xv.x + rv.x, v1 = xv.y + rv.y, v2 = xv.z + rv.z, v3 = xv.w + rv.w;
    float s1 = v0 + v1 + v2 + v3;
    float s2 = v0*v0 + v1*v1 + v2*v2 + v3*v3;

    __shared__ float rA[256], rB[256];
    rA[tid] = s1; rB[tid] = s2; __syncthreads();
    for (int s = 128; s > 0; s >>= 1) {
        if (tid < s) { rA[tid] += rA[tid + s]; rB[tid] += rB[tid + s]; }
        __syncthreads();
    }
    float mu = rA[0] * (1.0f / 1024.0f);
    float var = rB[0] * (1.0f / 1024.0f) - mu * mu;
    float rstd = rsqrtf(var + 1e-5f);

    const float4 gv = ((const float4*)g)[tid];
    const float4 bv = ((const float4*)bta)[tid];
    float4 o;
    o.x = (v0 - mu) * rstd * gv.x + bv.x;
    o.y = (v1 - mu) * rstd * gv.y + bv.y;
    o.z = (v2 - mu) * rstd * gv.z + bv.z;
    o.w = (v3 - mu) * rstd * gv.w + bv.w;
    ((float4*)(out + (size_t)r * DD))[tid] = o;
    float4 t = make_float4(tf32r(o.x), tf32r(o.y), tf32r(o.z), tf32r(o.w));
    ((float4*)(out_t + (size_t)r * DD))[tid] = t;
}

// ---------------- launch ----------------
extern "C" void kernel_launch(void* const* d_in, const int* in_sizes, int n_in,
                              void* d_out, int out_size) {
    (void)in_sizes; (void)n_in; (void)out_size;
    const int*   x    = (const int*)  d_in[0];
    const int*   sp   = (const int*)  d_in[1];
    const float* emb  = (const float*)d_in[2];
    const float* Wq   = (const float*)d_in[3];
    const float* bq   = (const float*)d_in[4];
    const float* Wk   = (const float*)d_in[5];
    const float* bk   = (const float*)d_in[6];
    const float* Wv   = (const float*)d_in[7];
    const float* bv   = (const float*)d_in[8];
    const float* Wo   = (const float*)d_in[9];
    const float* bo   = (const float*)d_in[10];
    const float* ln1g = (const float*)d_in[11];
    const float* ln1b = (const float*)d_in[12];
    const float* W1   = (const float*)d_in[13];
    const float* b1   = (const float*)d_in[14];
    const float* W2   = (const float*)d_in[15];
    const float* b2   = (const float*)d_in[16];
    const float* ln2g = (const float*)d_in[17];
    const float* ln2b = (const float*)d_in[18];
    const float* fcw  = (const float*)d_in[19];
    const float* fcb  = (const float*)d_in[20];
    float* out = (float*)d_out;

    float *h, *ht, *q, *k, *v, *attn, *tmp, *ffn;
    cudaGetSymbolAddress((void**)&h,    g_h);
    cudaGetSymbolAddress((void**)&ht,   g_ht);
    cudaGetSymbolAddress((void**)&q,    g_q);
    cudaGetSymbolAddress((void**)&k,    g_k);
    cudaGetSymbolAddress((void**)&v,    g_v);
    cudaGetSymbolAddress((void**)&attn, g_attn);
    cudaGetSymbolAddress((void**)&tmp,  g_tmp);
    cudaGetSymbolAddress((void**)&ffn,  g_ffn);

    static int attr_done = 0;
    if (!attr_done) {
        cudaFuncSetAttribute(gemm_tc,    cudaFuncAttributeMaxDynamicSharedMemorySize, GEMM_SMEM);
        cudaFuncSetAttribute(flash_attn, cudaFuncAttributeMaxDynamicSharedMemorySize, FA_SMEM);
        attr_done = 1;
    }

    embed_kernel<<<MTOK, 256>>>(x, emb, h, ht);

    for (int l = 0; l < LL; l++) {
        const float* Wql = Wq + (size_t)l * DD * DD;
        const float* Wkl = Wk + (size_t)l * DD * DD;
        const float* Wvl = Wv + (size_t)l * DD * DD;
        const float* Wol = Wo + (size_t)l * DD * DD;
        const float* W1l = W1 + (size_t)l * DD * DFFN;
        const float* W2l = W2 + (size_t)l * DFFN * DD;

        gemm_tc<<<dim3(MTOK/128, DD/128, 3), 256, GEMM_SMEM>>>(
            ht,
            Wql, bq + (size_t)l*DD, q,
            Wkl, bk + (size_t)l*DD, k,
            Wvl, bv + (size_t)l*DD, v,
            DD, DD, DD, DD, 4, (const int*)0);

        flash_attn<<<dim3(SS/128, 1, BB*HH), 256, FA_SMEM>>>(q, k, v, attn, sp);

        gemm_tc<<<dim3(MTOK/128, DD/128, 1), 256, GEMM_SMEM>>>(
            attn, Wol, bo + (size_t)l*DD, tmp,
            (const float*)0, (const float*)0, (float*)0,
            (const float*)0, (const float*)0, (float*)0,
            DD, DD, DD, DD, 0, (const int*)0);
        add_ln<<<MTOK, 256>>>(h, tmp, ln1g + (size_t)l*DD, ln1b + (size_t)l*DD, h, ht);

        gemm_tc<<<dim3(MTOK/128, DFFN/128, 1), 256, GEMM_SMEM>>>(
            ht, W1l, b1 + (size_t)l*DFFN, ffn,
            (const float*)0, (const float*)0, (float*)0,
            (const float*)0, (const float*)0, (float*)0,
            DD, DD, DFFN, DFFN, 1 | 4, (const int*)0);
        gemm_tc<<<dim3(MTOK/128, DD/128, 1), 256, GEMM_SMEM>>>(
            ffn, W2l, b2 + (size_t)l*DD, tmp,
            (const float*)0, (const float*)0, (float*)0,
            (const float*)0, (const float*)0, (float*)0,
            DFFN, DFFN, DD, DD, 0, (const int*)0);
        add_ln<<<MTOK, 256>>>(h, tmp, ln2g + (size_t)l*DD, ln2b + (size_t)l*DD, h, ht);
    }

    gemm_tc<<<dim3(MTOK/128, OUTV/128, 1), 256, GEMM_SMEM>>>(
        ht, fcw, fcb, out,
        (const float*)0, (const float*)0, (float*)0,
        (const float*)0, (const float*)0, (float*)0,
        DD, DD, OUTV, OUTV, 2, sp);
}